// round 8
// baseline (speedup 1.0000x reference)
#include <cuda_runtime.h>
#include <cuda_fp16.h>
#include <math.h>
#include <stdint.h>

#define BSZ   4
#define NPT   8192
#define CH    256
#define NPTS  (BSZ*NPT)      // 32768
#define QKVW  768
#define AP    8              // points per attention block (one per warp)

// -------------------- scratch (device globals; no cudaMalloc allowed) -----
__device__ __half g_h[NPTS*CH];          // LN out (half, feeds GEMMs)
__device__ __half g_qkvh[NPTS*QKVW];     // qkv in half
__device__ __half g_xattn[NPTS*CH];
__device__ float  g_x[NPTS*CH];          // residual stream (fp32)
__device__ __half g_mlp1[NPTS*1024];
__device__ __half g_wqkv16[CH*QKVW];
__device__ __half g_wproj16[CH*CH];
__device__ __half g_wm1_16[CH*1024];
__device__ __half g_wm2_16[1024*CH];
__device__ __half g_wd2t[CH*CH];         // w_d2 transposed: [c][j], half

// -------------------- fused weight conversion (single launch) -------------
#define NW_QKV  (CH*QKVW)     // 196608
#define NW_PROJ (CH*CH)       // 65536
#define NW_M1   (CH*1024)     // 262144
#define NW_M2   (1024*CH)     // 262144
#define NW_D2   (CH*CH)       // 65536
#define NW_TOT  (NW_QKV+NW_PROJ+NW_M1+NW_M2+NW_D2)  // 851968

__global__ void convert_all(const float* __restrict__ w_qkv,
                            const float* __restrict__ w_proj,
                            const float* __restrict__ w_m1,
                            const float* __restrict__ w_m2,
                            const float* __restrict__ w_d2,
                            __half* __restrict__ d_qkv, __half* __restrict__ d_proj,
                            __half* __restrict__ d_m1,  __half* __restrict__ d_m2,
                            __half* __restrict__ d_d2t)
{
    int i = blockIdx.x * 256 + threadIdx.x;
    int stride = gridDim.x * 256;
    for (; i < NW_TOT; i += stride) {
        int r = i;
        if (r < NW_QKV) { d_qkv[r] = __float2half(w_qkv[r]); continue; }
        r -= NW_QKV;
        if (r < NW_PROJ) { d_proj[r] = __float2half(w_proj[r]); continue; }
        r -= NW_PROJ;
        if (r < NW_M1) { d_m1[r] = __float2half(w_m1[r]); continue; }
        r -= NW_M1;
        if (r < NW_M2) { d_m2[r] = __float2half(w_m2[r]); continue; }
        r -= NW_M2;
        int c = r >> 8, j = r & 255;           // transpose w_d2
        d_d2t[r] = __float2half(w_d2[j*CH + c]);
    }
}

// -------------------- LayerNorm (warp per row, fp32 in, fp16 out) ---------
__global__ void __launch_bounds__(256)
ln_kernel(const float* __restrict__ x, const float* __restrict__ g,
          const float* __restrict__ b, __half* __restrict__ out)
{
    int warp = threadIdx.x >> 5, lane = threadIdx.x & 31;
    int row  = blockIdx.x * 8 + warp;
    const float* xr = x + (size_t)row*CH + lane*8;

    float v[8];
    *(float4*)(v)     = *(const float4*)(xr);
    *(float4*)(v + 4) = *(const float4*)(xr + 4);

    float s = 0.f;
    #pragma unroll
    for (int j = 0; j < 8; j++) s += v[j];
    #pragma unroll
    for (int o = 16; o > 0; o >>= 1) s += __shfl_xor_sync(0xffffffffu, s, o);
    float mean = s * (1.0f / CH);

    float d[8], ss = 0.f;
    #pragma unroll
    for (int j = 0; j < 8; j++) { d[j] = v[j] - mean; ss += d[j]*d[j]; }
    #pragma unroll
    for (int o = 16; o > 0; o >>= 1) ss += __shfl_xor_sync(0xffffffffu, ss, o);
    float rstd = rsqrtf(ss * (1.0f / CH) + 1e-5f);

    float gv[8], bv[8];
    *(float4*)(gv)     = *(const float4*)(g + lane*8);
    *(float4*)(gv + 4) = *(const float4*)(g + lane*8 + 4);
    *(float4*)(bv)     = *(const float4*)(b + lane*8);
    *(float4*)(bv + 4) = *(const float4*)(b + lane*8 + 4);

    __half2 o2[4];
    #pragma unroll
    for (int j = 0; j < 4; j++)
        o2[j] = __floats2half2_rn(d[2*j]*rstd*gv[2*j] + bv[2*j],
                                  d[2*j+1]*rstd*gv[2*j+1] + bv[2*j+1]);
    *(uint4*)(out + (size_t)row*CH + lane*8) = *(uint4*)o2;
}

// -------------------- fp16 tensor-core GEMM (128x256x32, 3-stage) ---------
// 8 warps = 2(M) x 4(N); warp tile 64x64 -> per k16 chunk: 8 LDSM feed
// 32 HMMA (4.0 mma/ldsm, up from 2.67).
__device__ __forceinline__ float gelu_exact(float v) { return v * normcdff(v); }

#define HBM 128
#define HBN 256
#define HBK 32
#define AS_STR 40     // HBK + 8 halves (80 B row: ldmatrix conflict-free)
#define BS_STR 264    // HBN + 8 halves (528 B row: 528%128=16 -> conflict-free)
#define STAGE_H (HBM*AS_STR + HBK*BS_STR)   // 13568 halves
#define HSMEM_BYTES (3*STAGE_H*2)           // 81408 B

__device__ __forceinline__ void mma16816(float* c, const uint32_t* a,
                                         uint32_t b0, uint32_t b1)
{
    asm volatile(
        "mma.sync.aligned.m16n8k16.row.col.f32.f16.f16.f32 "
        "{%0,%1,%2,%3}, {%4,%5,%6,%7}, {%8,%9}, {%0,%1,%2,%3};"
        : "+f"(c[0]), "+f"(c[1]), "+f"(c[2]), "+f"(c[3])
        : "r"(a[0]), "r"(a[1]), "r"(a[2]), "r"(a[3]), "r"(b0), "r"(b1));
}

template<int EPI, typename OutT>
__global__ void __launch_bounds__(256, 1)
hgemm(const __half* __restrict__ A, const __half* __restrict__ B,
      OutT* __restrict__ C, int M, int N, int K,
      const float* __restrict__ bias, const float* __restrict__ resid)
{
    extern __shared__ __half sh[];

    int tid  = threadIdx.x;
    int lane = tid & 31;
    int warp = tid >> 5;
    int wm   = warp & 1;
    int wn   = warp >> 1;
    int bm   = blockIdx.y * HBM;
    int bn   = blockIdx.x * HBN;

    const __half* Ag = A + (size_t)bm * K;
    const __half* Bg = B + bn;

    float acc[4][8][4];
    #pragma unroll
    for (int i = 0; i < 4; i++)
        #pragma unroll
        for (int j = 0; j < 8; j++)
            #pragma unroll
            for (int r = 0; r < 4; r++) acc[i][j][r] = 0.f;

    auto issue = [&](int kt, int buf) {
        __half* As = sh + buf * STAGE_H;
        __half* Bs = As + HBM * AS_STR;
        // A: 512 x 16B ops (2/thread)
        #pragma unroll
        for (int s = 0; s < 2; s++) {
            int c  = tid * 2 + s;
            int ar = c >> 2, ak = (c & 3) * 8;
            uint32_t da = (uint32_t)__cvta_generic_to_shared(As + ar*AS_STR + ak);
            const __half* ga = Ag + (size_t)ar * K + kt * HBK + ak;
            asm volatile("cp.async.cg.shared.global [%0], [%1], 16;\n"
                         :: "r"(da), "l"(ga));
        }
        // B: 1024 x 16B ops (4/thread)
        #pragma unroll
        for (int s = 0; s < 4; s++) {
            int c   = tid * 4 + s;
            int bk  = c >> 5, bnn = (c & 31) * 8;
            uint32_t db = (uint32_t)__cvta_generic_to_shared(Bs + bk*BS_STR + bnn);
            const __half* gb = Bg + (size_t)(kt * HBK + bk) * N + bnn;
            asm volatile("cp.async.cg.shared.global [%0], [%1], 16;\n"
                         :: "r"(db), "l"(gb));
        }
        asm volatile("cp.async.commit_group;\n");
    };

    int nt = K / HBK;
    issue(0, 0);
    issue(1, 1);
    asm volatile("cp.async.wait_group 1;\n");
    __syncthreads();

    for (int kt = 0; kt < nt; kt++) {
        int cur = kt % 3;
        bool more = (kt + 2) < nt;
        if (more) issue(kt + 2, (kt + 2) % 3);

        __half* As = sh + cur * STAGE_H;
        __half* Bs = As + HBM * AS_STR;

        #pragma unroll
        for (int kk = 0; kk < HBK; kk += 16) {
            uint32_t af[4][4];
            #pragma unroll
            for (int i = 0; i < 4; i++) {
                int row = wm * 64 + i * 16 + (lane & 15);
                int kc  = kk + (lane >> 4) * 8;
                uint32_t ad = (uint32_t)__cvta_generic_to_shared(As + row*AS_STR + kc);
                asm volatile(
                    "ldmatrix.sync.aligned.m8n8.x4.shared.b16 {%0,%1,%2,%3}, [%4];"
                    : "=r"(af[i][0]), "=r"(af[i][1]), "=r"(af[i][2]), "=r"(af[i][3])
                    : "r"(ad));
            }
            #pragma unroll
            for (int j = 0; j < 4; j++) {        // 4 n16 chunks = 64 cols
                uint32_t bf[4];
                int krow = kk + (lane & 15);
                int nc   = wn * 64 + j * 16 + (lane >> 4) * 8;
                uint32_t bd = (uint32_t)__cvta_generic_to_shared(Bs + krow*BS_STR + nc);
                asm volatile(
                    "ldmatrix.sync.aligned.m8n8.x4.trans.shared.b16 {%0,%1,%2,%3}, [%4];"
                    : "=r"(bf[0]), "=r"(bf[1]), "=r"(bf[2]), "=r"(bf[3])
                    : "r"(bd));
                #pragma unroll
                for (int i = 0; i < 4; i++) {
                    mma16816(acc[i][2*j],     af[i], bf[0], bf[1]);
                    mma16816(acc[i][2*j + 1], af[i], bf[2], bf[3]);
                }
            }
        }

        if (more) asm volatile("cp.async.wait_group 1;\n");
        else      asm volatile("cp.async.wait_group 0;\n");
        __syncthreads();
    }

    #pragma unroll
    for (int i = 0; i < 4; i++) {
        int row = bm + wm * 64 + i * 16 + (lane >> 2);
        #pragma unroll
        for (int jj = 0; jj < 8; jj++) {
            int col = bn + wn * 64 + (jj >> 1) * 16 + (jj & 1) * 8 + (lane & 3) * 2;
            float2 v0 = make_float2(acc[i][jj][0], acc[i][jj][1]);
            float2 v1 = make_float2(acc[i][jj][2], acc[i][jj][3]);
            if (EPI >= 1) {
                float2 bv = *(const float2*)&bias[col];
                v0.x += bv.x; v0.y += bv.y;
                v1.x += bv.x; v1.y += bv.y;
            }
            if (EPI == 1) {
                float2 r0 = *(const float2*)&resid[(size_t)row * N + col];
                float2 r1 = *(const float2*)&resid[(size_t)(row + 8) * N + col];
                v0.x += r0.x; v0.y += r0.y;
                v1.x += r1.x; v1.y += r1.y;
            }
            if (EPI == 2) {
                v0.x = gelu_exact(v0.x); v0.y = gelu_exact(v0.y);
                v1.x = gelu_exact(v1.x); v1.y = gelu_exact(v1.y);
            }
            if constexpr (sizeof(OutT) == 2) {
                *(__half2*)&C[(size_t)row * N + col]       = __floats2half2_rn(v0.x, v0.y);
                *(__half2*)&C[(size_t)(row + 8) * N + col] = __floats2half2_rn(v1.x, v1.y);
            } else {
                *(float2*)&C[(size_t)row * N + col]       = v0;
                *(float2*)&C[(size_t)(row + 8) * N + col] = v1;
            }
        }
    }
}

// -------------------- KNN attention: warp per point -----------------------
__global__ void __launch_bounds__(256)
attn_kernel(const __half* __restrict__ qkv, const int* __restrict__ nns,
            const float* __restrict__ xyz,
            const float* __restrict__ w_d1, const float* __restrict__ b_d1,
            const __half* __restrict__ w_d2t, const float* __restrict__ b_d2,
            __half* __restrict__ xattn)
{
    __shared__ __half s_u[AP][4*CH + 8];   // pe basis, half
    __shared__ float  s_av[AP][CH];        // attn-weighted V

    int tid  = threadIdx.x;
    int lane = tid & 31;
    int p    = tid >> 5;
    int pi   = blockIdx.x * AP + p;
    int bb   = pi >> 13;

    int nbr = 0; float rx = 0.f, ry = 0.f;
    if (lane < 16) {
        int j = nns[pi*32 + lane];
        nbr = (bb << 13) + j;
        rx = xyz[pi*2]     - xyz[nbr*2];
        ry = xyz[pi*2 + 1] - xyz[nbr*2 + 1];
    }

    float qf[8];
    {
        uint4 qv = *(const uint4*)(qkv + (size_t)pi*QKVW + lane*8);
        const __half2* qh = (const __half2*)&qv;
        #pragma unroll
        for (int i = 0; i < 4; i++) {
            float2 f = __half22float2(qh[i]);
            qf[2*i] = f.x; qf[2*i+1] = f.y;
        }
    }

    float attn[16];
    #pragma unroll
    for (int k = 0; k < 16; k++) {
        int rowk = __shfl_sync(0xffffffffu, nbr, k);
        uint4 kv = *(const uint4*)(qkv + (size_t)rowk*QKVW + CH + lane*8);
        const __half2* kh = (const __half2*)&kv;
        float pr = 0.f;
        #pragma unroll
        for (int i = 0; i < 4; i++) {
            float2 f = __half22float2(kh[i]);
            pr = fmaf(qf[2*i], f.x, pr);
            pr = fmaf(qf[2*i+1], f.y, pr);
        }
        pr += __shfl_xor_sync(0xffffffffu, pr, 4);
        pr += __shfl_xor_sync(0xffffffffu, pr, 2);
        pr += __shfl_xor_sync(0xffffffffu, pr, 1);
        attn[k] = pr * 0.125f;
    }

    float mx = -1e30f;
    #pragma unroll
    for (int k = 0; k < 16; k++) mx = fmaxf(mx, attn[k]);
    float sm = 0.f;
    #pragma unroll
    for (int k = 0; k < 16; k++) { attn[k] = __expf(attn[k] - mx); sm += attn[k]; }
    float inv = 1.f / sm;
    #pragma unroll
    for (int k = 0; k < 16; k++) attn[k] *= inv;

    float wd1x[8], wd1y[8], bd1v[8];
    #pragma unroll
    for (int j = 0; j < 8; j++) {
        int c = lane*8 + j;
        wd1x[j] = w_d1[c]; wd1y[j] = w_d1[CH + c]; bd1v[j] = b_d1[c];
    }

    float av[8], u[4][8];
    #pragma unroll
    for (int j = 0; j < 8; j++) {
        av[j] = 0.f;
        u[0][j] = u[1][j] = u[2][j] = u[3][j] = 0.f;
    }

    #pragma unroll
    for (int k = 0; k < 16; k++) {
        int   rowk = __shfl_sync(0xffffffffu, nbr, k);
        float rxk  = __shfl_sync(0xffffffffu, rx, k);
        float ryk  = __shfl_sync(0xffffffffu, ry, k);
        float a0 = __shfl_sync(0xffffffffu, attn[k], 0);
        float a1 = __shfl_sync(0xffffffffu, attn[k], 8);
        float a2 = __shfl_sync(0xffffffffu, attn[k], 16);
        float a3 = __shfl_sync(0xffffffffu, attn[k], 24);

        uint4 vv = *(const uint4*)(qkv + (size_t)rowk*QKVW + 2*CH + lane*8);
        const __half2* vh = (const __half2*)&vv;
        #pragma unroll
        for (int i = 0; i < 4; i++) {
            float2 f = __half22float2(vh[i]);
            #pragma unroll
            for (int q2 = 0; q2 < 2; q2++) {
                int j = 2*i + q2;
                float vf = q2 ? f.y : f.x;
                av[j] = fmaf(attn[k], vf, av[j]);
                float t = fmaxf(fmaf(rxk, wd1x[j], fmaf(ryk, wd1y[j], bd1v[j])), 0.f);
                u[0][j] = fmaf(a0, t, u[0][j]);
                u[1][j] = fmaf(a1, t, u[1][j]);
                u[2][j] = fmaf(a2, t, u[2][j]);
                u[3][j] = fmaf(a3, t, u[3][j]);
            }
        }
    }

    #pragma unroll
    for (int h = 0; h < 4; h++) {
        __half2 tmp[4];
        #pragma unroll
        for (int i = 0; i < 4; i++)
            tmp[i] = __floats2half2_rn(u[h][2*i], u[h][2*i+1]);
        *(uint4*)&s_u[p][h*CH + lane*8] = *(uint4*)tmp;
    }
    *(float4*)&s_av[p][lane*8]     = make_float4(av[0], av[1], av[2], av[3]);
    *(float4*)&s_av[p][lane*8 + 4] = make_float4(av[4], av[5], av[6], av[7]);
    __syncthreads();

    // block-wide pe projection: out_c += sum_j u[h(c), j] * w_d2[j, c]
    int c = tid;
    int h = c >> 6;
    __half2 acca[AP], accb[AP];
    #pragma unroll
    for (int q2 = 0; q2 < AP; q2++) {
        acca[q2] = __floats2half2_rn(0.f, 0.f);
        accb[q2] = __floats2half2_rn(0.f, 0.f);
    }
    const __half* wrow = w_d2t + (size_t)c * CH;
    #pragma unroll 4
    for (int j8 = 0; j8 < CH/8; j8++) {
        uint4 wv = *(const uint4*)(wrow + j8*8);
        const __half2* w2 = (const __half2*)&wv;
        #pragma unroll
        for (int q2 = 0; q2 < AP; q2++) {
            uint4 uv = *(const uint4*)&s_u[q2][h*CH + j8*8];
            const __half2* u2 = (const __half2*)&uv;
            acca[q2] = __hfma2(u2[0], w2[0], acca[q2]);
            accb[q2] = __hfma2(u2[1], w2[1], accb[q2]);
            acca[q2] = __hfma2(u2[2], w2[2], acca[q2]);
            accb[q2] = __hfma2(u2[3], w2[3], accb[q2]);
        }
    }
    float bd2 = b_d2[c];
    #pragma unroll
    for (int q2 = 0; q2 < AP; q2++) {
        float2 fa = __half22float2(acca[q2]);
        float2 fb = __half22float2(accb[q2]);
        float val = s_av[q2][c] + fa.x + fa.y + fb.x + fb.y + bd2;
        xattn[(size_t)(blockIdx.x*AP + q2)*CH + c] = __float2half(val);
    }
}

// -------------------- launch ----------------------------------------------
extern "C" void kernel_launch(void* const* d_in, const int* in_sizes, int n_in,
                              void* d_out, int out_size)
{
    const float* xyz      = (const float*)d_in[0];
    const float* xy_embed = (const float*)d_in[1];
    const int*   nns      = (const int*)  d_in[2];
    const float* ln1_g    = (const float*)d_in[3];
    const float* ln1_b    = (const float*)d_in[4];
    const float* w_qkv    = (const float*)d_in[5];
    const float* w_d1     = (const float*)d_in[6];
    const float* b_d1     = (const float*)d_in[7];
    const float* w_d2     = (const float*)d_in[8];
    const float* b_d2     = (const float*)d_in[9];
    const float* w_proj   = (const float*)d_in[10];
    const float* b_proj   = (const float*)d_in[11];
    const float* ln2_g    = (const float*)d_in[12];
    const float* ln2_b    = (const float*)d_in[13];
    const float* w_m1     = (const float*)d_in[14];
    const float* b_m1     = (const float*)d_in[15];
    const float* w_m2     = (const float*)d_in[16];
    const float* b_m2     = (const float*)d_in[17];
    float* out = (float*)d_out;

    __half *h, *qkvh, *xattn, *mlp1, *wqkv16, *wproj16, *wm1_16, *wm2_16, *wd2t;
    float *x;
    cudaGetSymbolAddress((void**)&h,       g_h);
    cudaGetSymbolAddress((void**)&qkvh,    g_qkvh);
    cudaGetSymbolAddress((void**)&xattn,   g_xattn);
    cudaGetSymbolAddress((void**)&x,       g_x);
    cudaGetSymbolAddress((void**)&mlp1,    g_mlp1);
    cudaGetSymbolAddress((void**)&wqkv16,  g_wqkv16);
    cudaGetSymbolAddress((void**)&wproj16, g_wproj16);
    cudaGetSymbolAddress((void**)&wm1_16,  g_wm1_16);
    cudaGetSymbolAddress((void**)&wm2_16,  g_wm2_16);
    cudaGetSymbolAddress((void**)&wd2t,    g_wd2t);

    cudaFuncSetAttribute(hgemm<0, __half>,
        cudaFuncAttributeMaxDynamicSharedMemorySize, HSMEM_BYTES);
    cudaFuncSetAttribute(hgemm<1, float>,
        cudaFuncAttributeMaxDynamicSharedMemorySize, HSMEM_BYTES);
    cudaFuncSetAttribute(hgemm<2, __half>,
        cudaFuncAttributeMaxDynamicSharedMemorySize, HSMEM_BYTES);

    // 0. all weight conversions in one launch
    convert_all<<<592, 256>>>(w_qkv, w_proj, w_m1, w_m2, w_d2,
                              wqkv16, wproj16, wm1_16, wm2_16, wd2t);

    // 1. LN1 -> half
    ln_kernel<<<NPTS/8, 256>>>(xy_embed, ln1_g, ln1_b, h);
    // 2. qkv = h @ w_qkv  (32768 x 768 x 256)
    hgemm<0, __half><<<dim3(QKVW/HBN, NPTS/HBM), 256, HSMEM_BYTES>>>(
        h, wqkv16, qkvh, NPTS, QKVW, CH, nullptr, nullptr);
    // 3. KNN attention (warp/point) + fused pe projection
    attn_kernel<<<NPTS/AP, 256>>>(qkvh, nns, xyz, w_d1, b_d1, wd2t, b_d2, xattn);
    // 4. x = xy_embed + xattn @ w_proj + b_proj  (fp32 residual)
    hgemm<1, float><<<dim3(CH/HBN, NPTS/HBM), 256, HSMEM_BYTES>>>(
        xattn, wproj16, x, NPTS, CH, CH, b_proj, xy_embed);
    // 5. LN2 -> half
    ln_kernel<<<NPTS/8, 256>>>(x, ln2_g, ln2_b, h);
    // 6. mlp1 = gelu(h @ w_m1 + b_m1)  (32768 x 1024 x 256)
    hgemm<2, __half><<<dim3(1024/HBN, NPTS/HBM), 256, HSMEM_BYTES>>>(
        h, wm1_16, mlp1, NPTS, 1024, CH, b_m1, nullptr);
    // 7. out = x + mlp1 @ w_m2 + b_m2  (32768 x 256 x 1024)
    hgemm<1, float><<<dim3(CH/HBN, NPTS/HBM), 256, HSMEM_BYTES>>>(
        mlp1, wm2_16, out, NPTS, CH, 1024, b_m2, x);
}

// round 9
// speedup vs baseline: 1.3563x; 1.3563x over previous
#include <cuda_runtime.h>
#include <cuda_fp16.h>
#include <math.h>
#include <stdint.h>

#define BSZ   4
#define NPT   8192
#define CH    256
#define NPTS  (BSZ*NPT)      // 32768
#define QKVW  768
#define AUW   1280           // [av(256) | U(1024)]

// -------------------- scratch (device globals; no cudaMalloc allowed) -----
__device__ __half g_h[NPTS*CH];          // LN out (half, feeds GEMMs)
__device__ __half g_qkvh[NPTS*QKVW];     // qkv in half
__device__ __half g_au[NPTS*AUW];        // [av | U] from attention
__device__ float  g_x[NPTS*CH];          // residual stream (fp32)
__device__ __half g_mlp1[NPTS*1024];
__device__ __half g_wqkv16[CH*QKVW];
__device__ __half g_wm1_16[CH*1024];
__device__ __half g_wm2_16[1024*CH];
__device__ __half g_wcomb[AUW*CH];       // [w_proj ; Wbig] rows x 256
__device__ float  g_bfold[CH];           // b_proj + b_d2 @ w_proj

// -------------------- fused weight conversion (single launch) -------------
#define NW_QKV  (CH*QKVW)     // 196608
#define NW_M1   (CH*1024)     // 262144
#define NW_M2   (1024*CH)     // 262144
#define NW_TOT  (NW_QKV+NW_M1+NW_M2)

__global__ void convert_all(const float* __restrict__ w_qkv,
                            const float* __restrict__ w_m1,
                            const float* __restrict__ w_m2,
                            __half* __restrict__ d_qkv,
                            __half* __restrict__ d_m1, __half* __restrict__ d_m2)
{
    int i = blockIdx.x * 256 + threadIdx.x;
    int stride = gridDim.x * 256;
    for (; i < NW_TOT; i += stride) {
        int r = i;
        if (r < NW_QKV) { d_qkv[r] = __float2half(w_qkv[r]); continue; }
        r -= NW_QKV;
        if (r < NW_M1) { d_m1[r] = __float2half(w_m1[r]); continue; }
        r -= NW_M1;
        d_m2[r] = __float2half(w_m2[r]);
    }
}

// -------------------- fold: wcomb = [w_proj ; blockdiag(w_d2) @ w_proj] ---
// rows 0..255:            wcomb[r, c] = w_proj[r, c]
// rows 256+h*256+j:       wcomb[., c] = sum_{cc<64} w_d2[j, h*64+cc] * w_proj[h*64+cc, c]
__global__ void fold_kernel(const float* __restrict__ w_d2,
                            const float* __restrict__ w_proj,
                            __half* __restrict__ wcomb)
{
    int i = blockIdx.x * 256 + threadIdx.x;   // i = r*256 + c
    if (i >= AUW*CH) return;
    int r = i >> 8, c = i & 255;
    if (r < 256) {
        wcomb[i] = __float2half(w_proj[r*CH + c]);
    } else {
        int h = (r - 256) >> 8, j = (r - 256) & 255;
        float acc = 0.f;
        #pragma unroll 8
        for (int cc = 0; cc < 64; cc++) {
            int col = h*64 + cc;
            acc = fmaf(w_d2[j*CH + col], w_proj[col*CH + c], acc);
        }
        wcomb[i] = __float2half(acc);
    }
}

__global__ void bfold_kernel(const float* __restrict__ b_d2,
                             const float* __restrict__ w_proj,
                             const float* __restrict__ b_proj,
                             float* __restrict__ bfold)
{
    int c = threadIdx.x;
    float acc = b_proj[c];
    for (int cc = 0; cc < CH; cc++)
        acc = fmaf(b_d2[cc], w_proj[cc*CH + c], acc);
    bfold[c] = acc;
}

// -------------------- LayerNorm (warp per row, fp32 in, fp16 out) ---------
__global__ void __launch_bounds__(256)
ln_kernel(const float* __restrict__ x, const float* __restrict__ g,
          const float* __restrict__ b, __half* __restrict__ out)
{
    int warp = threadIdx.x >> 5, lane = threadIdx.x & 31;
    int row  = blockIdx.x * 8 + warp;
    const float* xr = x + (size_t)row*CH + lane*8;

    float v[8];
    *(float4*)(v)     = *(const float4*)(xr);
    *(float4*)(v + 4) = *(const float4*)(xr + 4);

    float s = 0.f;
    #pragma unroll
    for (int j = 0; j < 8; j++) s += v[j];
    #pragma unroll
    for (int o = 16; o > 0; o >>= 1) s += __shfl_xor_sync(0xffffffffu, s, o);
    float mean = s * (1.0f / CH);

    float d[8], ss = 0.f;
    #pragma unroll
    for (int j = 0; j < 8; j++) { d[j] = v[j] - mean; ss += d[j]*d[j]; }
    #pragma unroll
    for (int o = 16; o > 0; o >>= 1) ss += __shfl_xor_sync(0xffffffffu, ss, o);
    float rstd = rsqrtf(ss * (1.0f / CH) + 1e-5f);

    float gv[8], bv[8];
    *(float4*)(gv)     = *(const float4*)(g + lane*8);
    *(float4*)(gv + 4) = *(const float4*)(g + lane*8 + 4);
    *(float4*)(bv)     = *(const float4*)(b + lane*8);
    *(float4*)(bv + 4) = *(const float4*)(b + lane*8 + 4);

    __half2 o2[4];
    #pragma unroll
    for (int j = 0; j < 4; j++)
        o2[j] = __floats2half2_rn(d[2*j]*rstd*gv[2*j] + bv[2*j],
                                  d[2*j+1]*rstd*gv[2*j+1] + bv[2*j+1]);
    *(uint4*)(out + (size_t)row*CH + lane*8) = *(uint4*)o2;
}

// -------------------- fp16 tensor-core GEMM (128x128x32, 3-stage) ---------
// (R6 proven configuration)
__device__ __forceinline__ float gelu_exact(float v) { return v * normcdff(v); }

#define HBM 128
#define HBN 128
#define HBK 32
#define AS_STR 40     // HBK + 8 halves
#define BS_STR 136    // HBN + 8 halves
#define STAGE_H (HBM*AS_STR + HBK*BS_STR)   // 9472 halves
#define HSMEM_BYTES (3*STAGE_H*2)           // 56832 B

__device__ __forceinline__ void mma16816(float* c, const uint32_t* a,
                                         uint32_t b0, uint32_t b1)
{
    asm volatile(
        "mma.sync.aligned.m16n8k16.row.col.f32.f16.f16.f32 "
        "{%0,%1,%2,%3}, {%4,%5,%6,%7}, {%8,%9}, {%0,%1,%2,%3};"
        : "+f"(c[0]), "+f"(c[1]), "+f"(c[2]), "+f"(c[3])
        : "r"(a[0]), "r"(a[1]), "r"(a[2]), "r"(a[3]), "r"(b0), "r"(b1));
}

template<int EPI, typename OutT>
__global__ void __launch_bounds__(256)
hgemm(const __half* __restrict__ A, const __half* __restrict__ B,
      OutT* __restrict__ C, int M, int N, int K,
      const float* __restrict__ bias, const float* __restrict__ resid)
{
    extern __shared__ __half sh[];

    int tid  = threadIdx.x;
    int lane = tid & 31;
    int warp = tid >> 5;
    int wm   = warp & 1;
    int wn   = warp >> 1;
    int bm   = blockIdx.y * HBM;
    int bn   = blockIdx.x * HBN;

    const __half* Ag = A + (size_t)bm * K;
    const __half* Bg = B + bn;

    float acc[4][4][4];
    #pragma unroll
    for (int i = 0; i < 4; i++)
        #pragma unroll
        for (int j = 0; j < 4; j++)
            #pragma unroll
            for (int r = 0; r < 4; r++) acc[i][j][r] = 0.f;

    auto issue = [&](int kt, int buf) {
        __half* As = sh + buf * STAGE_H;
        __half* Bs = As + HBM * AS_STR;
        #pragma unroll
        for (int s = 0; s < 2; s++) {
            int c  = tid * 2 + s;
            int ar = c >> 2, ak = (c & 3) * 8;
            uint32_t da = (uint32_t)__cvta_generic_to_shared(As + ar*AS_STR + ak);
            const __half* ga = Ag + (size_t)ar * K + kt * HBK + ak;
            asm volatile("cp.async.cg.shared.global [%0], [%1], 16;\n"
                         :: "r"(da), "l"(ga));
            int bk = c >> 4, bnn = (c & 15) * 8;
            uint32_t db = (uint32_t)__cvta_generic_to_shared(Bs + bk*BS_STR + bnn);
            const __half* gb = Bg + (size_t)(kt * HBK + bk) * N + bnn;
            asm volatile("cp.async.cg.shared.global [%0], [%1], 16;\n"
                         :: "r"(db), "l"(gb));
        }
        asm volatile("cp.async.commit_group;\n");
    };

    int nt = K / HBK;
    issue(0, 0);
    issue(1, 1);
    asm volatile("cp.async.wait_group 1;\n");
    __syncthreads();

    for (int kt = 0; kt < nt; kt++) {
        int cur = kt % 3;
        bool more = (kt + 2) < nt;
        if (more) issue(kt + 2, (kt + 2) % 3);

        __half* As = sh + cur * STAGE_H;
        __half* Bs = As + HBM * AS_STR;

        #pragma unroll
        for (int kk = 0; kk < HBK; kk += 16) {
            uint32_t af[4][4];
            #pragma unroll
            for (int i = 0; i < 4; i++) {
                int row = wm * 64 + i * 16 + (lane & 15);
                int kc  = kk + (lane >> 4) * 8;
                uint32_t ad = (uint32_t)__cvta_generic_to_shared(As + row*AS_STR + kc);
                asm volatile(
                    "ldmatrix.sync.aligned.m8n8.x4.shared.b16 {%0,%1,%2,%3}, [%4];"
                    : "=r"(af[i][0]), "=r"(af[i][1]), "=r"(af[i][2]), "=r"(af[i][3])
                    : "r"(ad));
            }
            #pragma unroll
            for (int j = 0; j < 2; j++) {
                uint32_t bf[4];
                int krow = kk + (lane & 15);
                int nc   = wn * 32 + j * 16 + (lane >> 4) * 8;
                uint32_t bd = (uint32_t)__cvta_generic_to_shared(Bs + krow*BS_STR + nc);
                asm volatile(
                    "ldmatrix.sync.aligned.m8n8.x4.trans.shared.b16 {%0,%1,%2,%3}, [%4];"
                    : "=r"(bf[0]), "=r"(bf[1]), "=r"(bf[2]), "=r"(bf[3])
                    : "r"(bd));
                #pragma unroll
                for (int i = 0; i < 4; i++) {
                    mma16816(acc[i][2*j],     af[i], bf[0], bf[1]);
                    mma16816(acc[i][2*j + 1], af[i], bf[2], bf[3]);
                }
            }
        }

        if (more) asm volatile("cp.async.wait_group 1;\n");
        else      asm volatile("cp.async.wait_group 0;\n");
        __syncthreads();
    }

    #pragma unroll
    for (int i = 0; i < 4; i++) {
        int row = bm + wm * 64 + i * 16 + (lane >> 2);
        #pragma unroll
        for (int jj = 0; jj < 4; jj++) {
            int col = bn + wn * 32 + (jj >> 1) * 16 + (jj & 1) * 8 + (lane & 3) * 2;
            float2 v0 = make_float2(acc[i][jj][0], acc[i][jj][1]);
            float2 v1 = make_float2(acc[i][jj][2], acc[i][jj][3]);
            if (EPI >= 1) {
                float2 bv = *(const float2*)&bias[col];
                v0.x += bv.x; v0.y += bv.y;
                v1.x += bv.x; v1.y += bv.y;
            }
            if (EPI == 1) {
                float2 r0 = *(const float2*)&resid[(size_t)row * N + col];
                float2 r1 = *(const float2*)&resid[(size_t)(row + 8) * N + col];
                v0.x += r0.x; v0.y += r0.y;
                v1.x += r1.x; v1.y += r1.y;
            }
            if (EPI == 2) {
                v0.x = gelu_exact(v0.x); v0.y = gelu_exact(v0.y);
                v1.x = gelu_exact(v1.x); v1.y = gelu_exact(v1.y);
            }
            if constexpr (sizeof(OutT) == 2) {
                *(__half2*)&C[(size_t)row * N + col]       = __floats2half2_rn(v0.x, v0.y);
                *(__half2*)&C[(size_t)(row + 8) * N + col] = __floats2half2_rn(v1.x, v1.y);
            } else {
                *(float2*)&C[(size_t)row * N + col]       = v0;
                *(float2*)&C[(size_t)(row + 8) * N + col] = v1;
            }
        }
    }
}

// -------------------- KNN attention: warp per point, pure gather ----------
// Emits per-point row [av(256) | U(1024)] in half. No shared memory, no
// block barriers — the pe projection is folded into the au-GEMM via Wbig.
__global__ void __launch_bounds__(512)
attn_kernel(const __half* __restrict__ qkv, const int* __restrict__ nns,
            const float* __restrict__ xyz,
            const float* __restrict__ w_d1, const float* __restrict__ b_d1,
            __half* __restrict__ au)
{
    int lane = threadIdx.x & 31;
    int p    = threadIdx.x >> 5;
    int pi   = blockIdx.x * 16 + p;
    int bb   = pi >> 13;

    int nbr = 0; float rx = 0.f, ry = 0.f;
    if (lane < 16) {
        int j = nns[pi*32 + lane];
        nbr = (bb << 13) + j;
        rx = xyz[pi*2]     - xyz[nbr*2];
        ry = xyz[pi*2 + 1] - xyz[nbr*2 + 1];
    }

    float qf[8];
    {
        uint4 qv = *(const uint4*)(qkv + (size_t)pi*QKVW + lane*8);
        const __half2* qh = (const __half2*)&qv;
        #pragma unroll
        for (int i = 0; i < 4; i++) {
            float2 f = __half22float2(qh[i]);
            qf[2*i] = f.x; qf[2*i+1] = f.y;
        }
    }

    float attn[16];
    #pragma unroll
    for (int k = 0; k < 16; k++) {
        int rowk = __shfl_sync(0xffffffffu, nbr, k);
        uint4 kv = *(const uint4*)(qkv + (size_t)rowk*QKVW + CH + lane*8);
        const __half2* kh = (const __half2*)&kv;
        float pr = 0.f;
        #pragma unroll
        for (int i = 0; i < 4; i++) {
            float2 f = __half22float2(kh[i]);
            pr = fmaf(qf[2*i], f.x, pr);
            pr = fmaf(qf[2*i+1], f.y, pr);
        }
        pr += __shfl_xor_sync(0xffffffffu, pr, 4);
        pr += __shfl_xor_sync(0xffffffffu, pr, 2);
        pr += __shfl_xor_sync(0xffffffffu, pr, 1);
        attn[k] = pr * 0.125f;
    }

    float mx = -1e30f;
    #pragma unroll
    for (int k = 0; k < 16; k++) mx = fmaxf(mx, attn[k]);
    float sm = 0.f;
    #pragma unroll
    for (int k = 0; k < 16; k++) { attn[k] = __expf(attn[k] - mx); sm += attn[k]; }
    float inv = 1.f / sm;
    #pragma unroll
    for (int k = 0; k < 16; k++) attn[k] *= inv;

    float wd1x[8], wd1y[8], bd1v[8];
    #pragma unroll
    for (int j = 0; j < 8; j++) {
        int c = lane*8 + j;
        wd1x[j] = w_d1[c]; wd1y[j] = w_d1[CH + c]; bd1v[j] = b_d1[c];
    }

    float av[8], u[4][8];
    #pragma unroll
    for (int j = 0; j < 8; j++) {
        av[j] = 0.f;
        u[0][j] = u[1][j] = u[2][j] = u[3][j] = 0.f;
    }

    #pragma unroll
    for (int k = 0; k < 16; k++) {
        int   rowk = __shfl_sync(0xffffffffu, nbr, k);
        float rxk  = __shfl_sync(0xffffffffu, rx, k);
        float ryk  = __shfl_sync(0xffffffffu, ry, k);
        float a0 = __shfl_sync(0xffffffffu, attn[k], 0);
        float a1 = __shfl_sync(0xffffffffu, attn[k], 8);
        float a2 = __shfl_sync(0xffffffffu, attn[k], 16);
        float a3 = __shfl_sync(0xffffffffu, attn[k], 24);

        uint4 vv = *(const uint4*)(qkv + (size_t)rowk*QKVW + 2*CH + lane*8);
        const __half2* vh = (const __half2*)&vv;
        #pragma unroll
        for (int i = 0; i < 4; i++) {
            float2 f = __half22float2(vh[i]);
            #pragma unroll
            for (int q2 = 0; q2 < 2; q2++) {
                int j = 2*i + q2;
                float vf = q2 ? f.y : f.x;
                av[j] = fmaf(attn[k], vf, av[j]);
                float t = fmaxf(fmaf(rxk, wd1x[j], fmaf(ryk, wd1y[j], bd1v[j])), 0.f);
                u[0][j] = fmaf(a0, t, u[0][j]);
                u[1][j] = fmaf(a1, t, u[1][j]);
                u[2][j] = fmaf(a2, t, u[2][j]);
                u[3][j] = fmaf(a3, t, u[3][j]);
            }
        }
    }

    // write [av | U] row: all stores coalesced (uint4 per lane)
    size_t rowo = (size_t)pi * AUW;
    {
        __half2 t4[4];
        #pragma unroll
        for (int i = 0; i < 4; i++)
            t4[i] = __floats2half2_rn(av[2*i], av[2*i+1]);
        *(uint4*)(au + rowo + lane*8) = *(uint4*)t4;
    }
    #pragma unroll
    for (int h = 0; h < 4; h++) {
        __half2 t4[4];
        #pragma unroll
        for (int i = 0; i < 4; i++)
            t4[i] = __floats2half2_rn(u[h][2*i], u[h][2*i+1]);
        *(uint4*)(au + rowo + 256 + h*256 + lane*8) = *(uint4*)t4;
    }
}

// -------------------- launch ----------------------------------------------
extern "C" void kernel_launch(void* const* d_in, const int* in_sizes, int n_in,
                              void* d_out, int out_size)
{
    const float* xyz      = (const float*)d_in[0];
    const float* xy_embed = (const float*)d_in[1];
    const int*   nns      = (const int*)  d_in[2];
    const float* ln1_g    = (const float*)d_in[3];
    const float* ln1_b    = (const float*)d_in[4];
    const float* w_qkv    = (const float*)d_in[5];
    const float* w_d1     = (const float*)d_in[6];
    const float* b_d1     = (const float*)d_in[7];
    const float* w_d2     = (const float*)d_in[8];
    const float* b_d2     = (const float*)d_in[9];
    const float* w_proj   = (const float*)d_in[10];
    const float* b_proj   = (const float*)d_in[11];
    const float* ln2_g    = (const float*)d_in[12];
    const float* ln2_b    = (const float*)d_in[13];
    const float* w_m1     = (const float*)d_in[14];
    const float* b_m1     = (const float*)d_in[15];
    const float* w_m2     = (const float*)d_in[16];
    const float* b_m2     = (const float*)d_in[17];
    float* out = (float*)d_out;

    __half *h, *qkvh, *au, *mlp1, *wqkv16, *wm1_16, *wm2_16, *wcomb;
    float *x, *bfold;
    cudaGetSymbolAddress((void**)&h,      g_h);
    cudaGetSymbolAddress((void**)&qkvh,   g_qkvh);
    cudaGetSymbolAddress((void**)&au,     g_au);
    cudaGetSymbolAddress((void**)&x,      g_x);
    cudaGetSymbolAddress((void**)&mlp1,   g_mlp1);
    cudaGetSymbolAddress((void**)&wqkv16, g_wqkv16);
    cudaGetSymbolAddress((void**)&wm1_16, g_wm1_16);
    cudaGetSymbolAddress((void**)&wm2_16, g_wm2_16);
    cudaGetSymbolAddress((void**)&wcomb,  g_wcomb);
    cudaGetSymbolAddress((void**)&bfold,  g_bfold);

    cudaFuncSetAttribute(hgemm<0, __half>,
        cudaFuncAttributeMaxDynamicSharedMemorySize, HSMEM_BYTES);
    cudaFuncSetAttribute(hgemm<1, float>,
        cudaFuncAttributeMaxDynamicSharedMemorySize, HSMEM_BYTES);
    cudaFuncSetAttribute(hgemm<2, __half>,
        cudaFuncAttributeMaxDynamicSharedMemorySize, HSMEM_BYTES);

    // 0. prologue: conversions + fold (all independent, tiny)
    convert_all<<<592, 256>>>(w_qkv, w_m1, w_m2, wqkv16, wm1_16, wm2_16);
    fold_kernel<<<(AUW*CH + 255)/256, 256>>>(w_d2, w_proj, wcomb);
    bfold_kernel<<<1, 256>>>(b_d2, w_proj, b_proj, bfold);

    // 1. LN1 -> half
    ln_kernel<<<NPTS/8, 256>>>(xy_embed, ln1_g, ln1_b, h);
    // 2. qkv = h @ w_qkv  (32768 x 768 x 256)
    hgemm<0, __half><<<dim3(QKVW/HBN, NPTS/HBM), 256, HSMEM_BYTES>>>(
        h, wqkv16, qkvh, NPTS, QKVW, CH, nullptr, nullptr);
    // 3. KNN attention -> [av | U]
    attn_kernel<<<NPTS/16, 512>>>(qkvh, nns, xyz, w_d1, b_d1, au);
    // 4. x = xy_embed + [av|U] @ wcomb + bfold   (32768 x 256 x 1280)
    hgemm<1, float><<<dim3(CH/HBN, NPTS/HBM), 256, HSMEM_BYTES>>>(
        au, wcomb, x, NPTS, CH, AUW, bfold, xy_embed);
    // 5. LN2 -> half
    ln_kernel<<<NPTS/8, 256>>>(x, ln2_g, ln2_b, h);
    // 6. mlp1 = gelu(h @ w_m1 + b_m1)  (32768 x 1024 x 256)
    hgemm<2, __half><<<dim3(1024/HBN, NPTS/HBM), 256, HSMEM_BYTES>>>(
        h, wm1_16, mlp1, NPTS, 1024, CH, b_m1, nullptr);
    // 7. out = x + mlp1 @ w_m2 + b_m2  (32768 x 256 x 1024)
    hgemm<1, float><<<dim3(CH/HBN, NPTS/HBM), 256, HSMEM_BYTES>>>(
        mlp1, wm2_16, out, NPTS, CH, 1024, b_m2, x);
}